// round 1
// baseline (speedup 1.0000x reference)
#include <cuda_runtime.h>
#include <cuda_bf16.h>

#define N_NODES 20000
#define M_EDGES 5000
#define D_IN    256
#define D_OUT   512
#define NNZ_CAP 5400000   // mean nnz = 5.0e6, sigma ~2.2e3 -> huge margin

// ---------------- scratch (static device globals; no runtime allocation) ----
__device__ int g_cnt_e[M_EDGES];
__device__ int g_cnt_v[N_NODES];
__device__ int g_eoff[M_EDGES + 1];
__device__ int g_voff[N_NODES + 1];
__device__ int g_ecur[M_EDGES];
__device__ int g_vcur[N_NODES];
__device__ int g_edge_nodes[NNZ_CAP];   // per-edge node lists (CSC of H)
__device__ int g_node_edges[NNZ_CAP];   // per-node edge lists (CSR of H)
__device__ __nv_bfloat162 g_xbf[N_NODES * (D_IN / 2)];  // x in bf16 (L2-resident, 10 MB)
__device__ __nv_bfloat162 g_A[M_EDGES * (D_IN / 2)];    // edge feats bf16 (2.5 MB)
__device__ float g_B[N_NODES * D_IN];                   // node agg fp32 (20 MB)
__device__ float g_h[N_NODES * D_OUT];                  // pre-LN hidden (40 MB)

// ---------------- 0: zero counters/cursors (idempotent per graph replay) ----
__global__ void k_zero() {
    int i = blockIdx.x * blockDim.x + threadIdx.x;
    if (i < M_EDGES) { g_cnt_e[i] = 0; g_ecur[i] = 0; }
    if (i < N_NODES) { g_cnt_v[i] = 0; g_vcur[i] = 0; }
}

// ---------------- 1: cast x to bf16 --------------------------------------
__global__ void k_xcast(const float2* __restrict__ x2) {
    int i = blockIdx.x * blockDim.x + threadIdx.x;
    if (i < N_NODES * (D_IN / 2)) {
        float2 v = x2[i];
        g_xbf[i] = __floats2bfloat162_rn(v.x, v.y);
    }
}

// ---------------- 2: count nonzeros per edge / per node -------------------
// H is [N, M] row-major; M = 5000 divisible by 4, so float4 never crosses rows.
__global__ void k_count(const float4* __restrict__ H4) {
    int i = blockIdx.x * blockDim.x + threadIdx.x;
    const int total = N_NODES * (M_EDGES / 4);
    if (i >= total) return;
    float4 v = H4[i];
    int base = i * 4;
    int n = base / M_EDGES;
    int m = base - n * M_EDGES;
    int vc = 0;
    if (v.x != 0.f) { atomicAdd(&g_cnt_e[m + 0], 1); vc++; }
    if (v.y != 0.f) { atomicAdd(&g_cnt_e[m + 1], 1); vc++; }
    if (v.z != 0.f) { atomicAdd(&g_cnt_e[m + 2], 1); vc++; }
    if (v.w != 0.f) { atomicAdd(&g_cnt_e[m + 3], 1); vc++; }
    if (vc) atomicAdd(&g_cnt_v[n], vc);
}

// ---------------- 3: exclusive scan (single block, chunked) ---------------
// which == 0: scan g_cnt_e -> g_eoff (len M); which == 1: g_cnt_v -> g_voff.
__global__ void k_scan(int which) {
    const int* cnt = which ? g_cnt_v : g_cnt_e;
    int* off       = which ? g_voff  : g_eoff;
    int len        = which ? N_NODES : M_EDGES;
    __shared__ int sdata[1024];
    __shared__ int s_running;
    if (threadIdx.x == 0) s_running = 0;
    __syncthreads();
    for (int base = 0; base < len; base += 1024) {
        int i = base + threadIdx.x;
        int v = (i < len) ? cnt[i] : 0;
        sdata[threadIdx.x] = v;
        __syncthreads();
        #pragma unroll
        for (int o = 1; o < 1024; o <<= 1) {
            int t = (threadIdx.x >= o) ? sdata[threadIdx.x - o] : 0;
            __syncthreads();
            sdata[threadIdx.x] += t;
            __syncthreads();
        }
        int incl = sdata[threadIdx.x];
        if (i < len) off[i] = s_running + incl - v;  // exclusive
        __syncthreads();
        if (threadIdx.x == 1023) s_running += sdata[1023];
        __syncthreads();
    }
    if (threadIdx.x == 0) off[len] = s_running;
}

// ---------------- 4: fill adjacency lists ---------------------------------
__global__ void k_fill(const float4* __restrict__ H4) {
    int i = blockIdx.x * blockDim.x + threadIdx.x;
    const int total = N_NODES * (M_EDGES / 4);
    if (i >= total) return;
    float4 v = H4[i];
    int base = i * 4;
    int n = base / M_EDGES;
    int m = base - n * M_EDGES;
    float vals[4] = {v.x, v.y, v.z, v.w};
    #pragma unroll
    for (int j = 0; j < 4; ++j) {
        if (vals[j] != 0.f) {
            int mj = m + j;
            int p = atomicAdd(&g_ecur[mj], 1);
            int idx = g_eoff[mj] + p;
            if (idx < NNZ_CAP) g_edge_nodes[idx] = n;
            int q = atomicAdd(&g_vcur[n], 1);
            int idx2 = g_voff[n] + q;
            if (idx2 < NNZ_CAP) g_node_edges[idx2] = mj;
        }
    }
}

// ---------------- 5: edge aggregation A[m,:] = mean_{n in e(m)} x[n,:] ----
// 1 block per edge, 128 threads, each thread owns 2 dims (bf16x2).
__global__ void __launch_bounds__(128) k_edge_agg() {
    int m = blockIdx.x;
    int beg = g_eoff[m];
    int end = g_eoff[m + 1];
    if (end > NNZ_CAP) end = NNZ_CAP;
    if (beg > NNZ_CAP) beg = NNZ_CAP;
    int k = threadIdx.x;  // 0..127
    float sx = 0.f, sy = 0.f;
    int i = beg;
    for (; i + 4 <= end; i += 4) {
        int n0 = g_edge_nodes[i];
        int n1 = g_edge_nodes[i + 1];
        int n2 = g_edge_nodes[i + 2];
        int n3 = g_edge_nodes[i + 3];
        float2 f0 = __bfloat1622float2(g_xbf[n0 * 128 + k]);
        float2 f1 = __bfloat1622float2(g_xbf[n1 * 128 + k]);
        float2 f2 = __bfloat1622float2(g_xbf[n2 * 128 + k]);
        float2 f3 = __bfloat1622float2(g_xbf[n3 * 128 + k]);
        sx += (f0.x + f1.x) + (f2.x + f3.x);
        sy += (f0.y + f1.y) + (f2.y + f3.y);
    }
    for (; i < end; ++i) {
        int n0 = g_edge_nodes[i];
        float2 f0 = __bfloat1622float2(g_xbf[n0 * 128 + k]);
        sx += f0.x; sy += f0.y;
    }
    float inv = 1.f / fmaxf((float)g_cnt_e[m], 1.f);
    g_A[m * 128 + k] = __floats2bfloat162_rn(sx * inv, sy * inv);
}

// ---------------- 6: node aggregation B[n,:] = mean_{m in e(n)} A[m,:] ----
__global__ void __launch_bounds__(128) k_node_agg() {
    int n = blockIdx.x;
    int beg = g_voff[n];
    int end = g_voff[n + 1];
    if (end > NNZ_CAP) end = NNZ_CAP;
    if (beg > NNZ_CAP) beg = NNZ_CAP;
    int k = threadIdx.x;
    float sx = 0.f, sy = 0.f;
    int i = beg;
    for (; i + 4 <= end; i += 4) {
        int m0 = g_node_edges[i];
        int m1 = g_node_edges[i + 1];
        int m2 = g_node_edges[i + 2];
        int m3 = g_node_edges[i + 3];
        float2 f0 = __bfloat1622float2(g_A[m0 * 128 + k]);
        float2 f1 = __bfloat1622float2(g_A[m1 * 128 + k]);
        float2 f2 = __bfloat1622float2(g_A[m2 * 128 + k]);
        float2 f3 = __bfloat1622float2(g_A[m3 * 128 + k]);
        sx += (f0.x + f1.x) + (f2.x + f3.x);
        sy += (f0.y + f1.y) + (f2.y + f3.y);
    }
    for (; i < end; ++i) {
        int m0 = g_node_edges[i];
        float2 f0 = __bfloat1622float2(g_A[m0 * 128 + k]);
        sx += f0.x; sy += f0.y;
    }
    float inv = 1.f / fmaxf((float)g_cnt_v[n], 1.f);
    reinterpret_cast<float2*>(g_B)[n * 128 + k] = make_float2(sx * inv, sy * inv);
}

// ---------------- 7: fused GEMM  h = B@W_node + x@W_res  (fp32) -----------
// Tile: 128 rows x 64 cols, BK=16, 256 threads, 8x4 per-thread microtile.
// K = 512 total: kb 0..15 uses (g_B, W_node), kb 16..31 uses (x, W_res).
#define BM 128
#define BN 64
#define BK 16
__global__ void __launch_bounds__(256) k_gemm(const float* __restrict__ x,
                                              const float* __restrict__ Wn,
                                              const float* __restrict__ Wr) {
    __shared__ float As[BK][BM];
    __shared__ float Bs[BK][BN];
    int tid = threadIdx.x;
    int rowBase = blockIdx.y * BM;
    int colBase = blockIdx.x * BN;
    int tm = tid >> 4;          // 0..15 -> rows tm*8 .. tm*8+7
    int tn = tid & 15;          // 0..15 -> cols tn*4 .. tn*4+3
    int am = tid >> 1;          // A-load row 0..127
    int ak0 = (tid & 1) * 8;    // A-load k-offset 0 or 8
    int wk = tid >> 4;          // W-load k 0..15
    int wn = (tid & 15) * 4;    // W-load col offset

    float acc[8][4];
    #pragma unroll
    for (int i = 0; i < 8; ++i)
        #pragma unroll
        for (int j = 0; j < 4; ++j) acc[i][j] = 0.f;

    for (int kb = 0; kb < 32; ++kb) {
        const float* Asrc = (kb < 16) ? g_B : x;
        const float* Wsrc = (kb < 16) ? Wn : Wr;
        int koff = (kb & 15) * BK;
        // stage loads into registers
        int arow = rowBase + am;
        float4 a0, a1;
        if (arow < N_NODES) {
            const float4* p = reinterpret_cast<const float4*>(Asrc + arow * D_IN + koff + ak0);
            a0 = p[0]; a1 = p[1];
        } else {
            a0 = make_float4(0.f, 0.f, 0.f, 0.f);
            a1 = make_float4(0.f, 0.f, 0.f, 0.f);
        }
        float4 w = *reinterpret_cast<const float4*>(Wsrc + (koff + wk) * D_OUT + colBase + wn);

        __syncthreads();  // previous iteration's compute done
        As[ak0 + 0][am] = a0.x; As[ak0 + 1][am] = a0.y;
        As[ak0 + 2][am] = a0.z; As[ak0 + 3][am] = a0.w;
        As[ak0 + 4][am] = a1.x; As[ak0 + 5][am] = a1.y;
        As[ak0 + 6][am] = a1.z; As[ak0 + 7][am] = a1.w;
        *reinterpret_cast<float4*>(&Bs[wk][wn]) = w;
        __syncthreads();

        #pragma unroll
        for (int k = 0; k < BK; ++k) {
            float4 ra0 = *reinterpret_cast<const float4*>(&As[k][tm * 8]);
            float4 ra1 = *reinterpret_cast<const float4*>(&As[k][tm * 8 + 4]);
            float4 rb  = *reinterpret_cast<const float4*>(&Bs[k][tn * 4]);
            float ra[8] = {ra0.x, ra0.y, ra0.z, ra0.w, ra1.x, ra1.y, ra1.z, ra1.w};
            float rbv[4] = {rb.x, rb.y, rb.z, rb.w};
            #pragma unroll
            for (int i = 0; i < 8; ++i)
                #pragma unroll
                for (int j = 0; j < 4; ++j)
                    acc[i][j] = fmaf(ra[i], rbv[j], acc[i][j]);
        }
    }

    #pragma unroll
    for (int i = 0; i < 8; ++i) {
        int row = rowBase + tm * 8 + i;
        if (row < N_NODES) {
            float* dst = g_h + row * D_OUT + colBase + tn * 4;
            dst[0] = acc[i][0]; dst[1] = acc[i][1];
            dst[2] = acc[i][2]; dst[3] = acc[i][3];
        }
    }
}

// ---------------- 8: LayerNorm over D_OUT + affine ------------------------
__global__ void __launch_bounds__(256) k_ln(const float* __restrict__ gamma,
                                            const float* __restrict__ beta,
                                            float* __restrict__ out) {
    int row = blockIdx.x;
    int t = threadIdx.x;  // 256 threads, 2 elems each
    const float* h = g_h + row * D_OUT;
    float v0 = h[t], v1 = h[t + 256];
    float s = v0 + v1;
    float sq = v0 * v0 + v1 * v1;
    #pragma unroll
    for (int o = 16; o > 0; o >>= 1) {
        s  += __shfl_xor_sync(0xffffffffu, s,  o);
        sq += __shfl_xor_sync(0xffffffffu, sq, o);
    }
    __shared__ float ssum[8], ssq[8];
    __shared__ float s_mu, s_inv;
    int w = t >> 5, l = t & 31;
    if (l == 0) { ssum[w] = s; ssq[w] = sq; }
    __syncthreads();
    if (t == 0) {
        float ts = 0.f, tq = 0.f;
        #pragma unroll
        for (int i = 0; i < 8; ++i) { ts += ssum[i]; tq += ssq[i]; }
        float mu = ts * (1.f / (float)D_OUT);
        float var = tq * (1.f / (float)D_OUT) - mu * mu;
        s_mu = mu;
        s_inv = rsqrtf(var + 1e-5f);
    }
    __syncthreads();
    float mu = s_mu, inv = s_inv;
    out[row * D_OUT + t]       = (v0 - mu) * inv * gamma[t]       + beta[t];
    out[row * D_OUT + t + 256] = (v1 - mu) * inv * gamma[t + 256] + beta[t + 256];
}

// ---------------- launch ---------------------------------------------------
extern "C" void kernel_launch(void* const* d_in, const int* in_sizes, int n_in,
                              void* d_out, int out_size) {
    const float* x     = (const float*)d_in[0];
    const float* H     = (const float*)d_in[1];
    const float* Wn    = (const float*)d_in[2];
    const float* Wr    = (const float*)d_in[3];
    const float* gamma = (const float*)d_in[4];
    const float* beta  = (const float*)d_in[5];
    float* out = (float*)d_out;

    k_zero<<<(N_NODES + 255) / 256, 256>>>();
    k_xcast<<<(N_NODES * (D_IN / 2) + 255) / 256, 256>>>((const float2*)x);

    const int total4 = N_NODES * (M_EDGES / 4);
    k_count<<<(total4 + 255) / 256, 256>>>((const float4*)H);
    k_scan<<<1, 1024>>>(0);   // edges
    k_scan<<<1, 1024>>>(1);   // nodes
    k_fill<<<(total4 + 255) / 256, 256>>>((const float4*)H);

    k_edge_agg<<<M_EDGES, 128>>>();
    k_node_agg<<<N_NODES, 128>>>();

    dim3 ggrid(D_OUT / BN, (N_NODES + BM - 1) / BM);
    k_gemm<<<ggrid, 256>>>(x, Wn, Wr);

    k_ln<<<N_NODES, 256>>>(gamma, beta, out);
}

// round 11
// speedup vs baseline: 1.4878x; 1.4878x over previous
#include <cuda_runtime.h>
#include <cuda_bf16.h>
#include <cstdint>

#define N_NODES 20000
#define M_EDGES 5000
#define D_IN    256
#define D_OUT   512
#define NNZ_CAP 5400000
#define N_PAD   20096            // 157 * 128

// ===================== scratch (static device globals) =====================
__device__ int g_cnt_e[M_EDGES];
__device__ int g_cnt_v[N_NODES];
__device__ int g_eoff[M_EDGES + 1];
__device__ int g_voff[N_NODES + 1];
__device__ int g_ecur[M_EDGES];
__device__ int g_vcur[N_NODES];
__device__ int g_npairs;
__device__ unsigned int g_pairs[NNZ_CAP];      // (n << 13) | m
__device__ int g_edge_nodes[NNZ_CAP];
__device__ int g_node_edges[NNZ_CAP];
__device__ __nv_bfloat162 g_xbf[N_NODES * (D_IN / 2)];
__device__ __nv_bfloat162 g_A[M_EDGES * (D_IN / 2)];
__device__ float g_B[N_NODES * D_IN];
__device__ float g_h[N_NODES * D_OUT];
__device__ __nv_bfloat16 g_Acat[(size_t)N_PAD * 1024];   // [Bbf | x_hi | x_hi | x_lo]
__device__ __nv_bfloat16 g_Wt[512 * 1024];               // transposed stacked weights

// ---------------- 0: zero counters ----------------------------------------
__global__ void k_zero() {
    int i = blockIdx.x * blockDim.x + threadIdx.x;
    if (i < M_EDGES) { g_cnt_e[i] = 0; g_ecur[i] = 0; }
    if (i < N_NODES) { g_cnt_v[i] = 0; g_vcur[i] = 0; }
    if (i == 0) g_npairs = 0;
}

// ---------------- 1: x -> bf16 --------------------------------------------
__global__ void k_xcast(const float2* __restrict__ x2) {
    int i = blockIdx.x * blockDim.x + threadIdx.x;
    if (i < N_NODES * (D_IN / 2)) {
        float2 v = x2[i];
        g_xbf[i] = __floats2bfloat162_rn(v.x, v.y);
    }
}

// ---------------- 2: single H pass: counts + packed nonzero pairs ----------
__global__ void k_count_pairs(const float4* __restrict__ H4) {
    int i = blockIdx.x * blockDim.x + threadIdx.x;
    const int total = N_NODES * (M_EDGES / 4);
    float4 v = make_float4(0.f, 0.f, 0.f, 0.f);
    if (i < total) v = H4[i];
    int base = i * 4;
    int n = base / M_EDGES;
    int m = base - n * M_EDGES;
    int ms[4]; int vc = 0;
    if (v.x != 0.f) { atomicAdd(&g_cnt_e[m + 0], 1); ms[vc++] = m + 0; }
    if (v.y != 0.f) { atomicAdd(&g_cnt_e[m + 1], 1); ms[vc++] = m + 1; }
    if (v.z != 0.f) { atomicAdd(&g_cnt_e[m + 2], 1); ms[vc++] = m + 2; }
    if (v.w != 0.f) { atomicAdd(&g_cnt_e[m + 3], 1); ms[vc++] = m + 3; }
    if (vc) atomicAdd(&g_cnt_v[n], vc);
    // warp-aggregated append
    int lane = threadIdx.x & 31;
    int incl = vc;
    #pragma unroll
    for (int o = 1; o < 32; o <<= 1) {
        int t = __shfl_up_sync(0xffffffffu, incl, o);
        if (lane >= o) incl += t;
    }
    int tot = __shfl_sync(0xffffffffu, incl, 31);
    int wbase = 0;
    if (lane == 31 && tot) wbase = atomicAdd(&g_npairs, tot);
    wbase = __shfl_sync(0xffffffffu, wbase, 31);
    int off = wbase + incl - vc;
    for (int j = 0; j < vc; ++j)
        if (off + j < NNZ_CAP) g_pairs[off + j] = ((unsigned)n << 13) | (unsigned)ms[j];
}

// ---------------- 3: both exclusive scans, O(n) ----------------------------
__device__ __forceinline__ void scan_phase(const int* cnt, int* off, int len,
                                           int* part) {
    int t = threadIdx.x;
    int chunk = (len + 1023) / 1024;
    int beg = t * chunk;
    int end = beg + chunk; if (end > len) end = len;
    if (beg > len) beg = len;
    int s = 0;
    for (int i = beg; i < end; ++i) s += cnt[i];
    part[t] = s;
    __syncthreads();
    #pragma unroll
    for (int o = 1; o < 1024; o <<= 1) {
        int v = (t >= o) ? part[t - o] : 0;
        __syncthreads();
        part[t] += v;
        __syncthreads();
    }
    int run = part[t] - s;   // exclusive prefix of this chunk
    for (int i = beg; i < end; ++i) { off[i] = run; run += cnt[i]; }
    if (t == 1023) off[len] = part[1023];
    __syncthreads();
}
__global__ void k_scan2() {
    __shared__ int part[1024];
    scan_phase(g_cnt_e, g_eoff, M_EDGES, part);
    scan_phase(g_cnt_v, g_voff, N_NODES, part);
}

// ---------------- 4: scatter pairs into CSC + CSR (grid-stride) ------------
__global__ void k_scatter() {
    int np = g_npairs; if (np > NNZ_CAP) np = NNZ_CAP;
    int stride = gridDim.x * blockDim.x;
    for (int i = blockIdx.x * blockDim.x + threadIdx.x; i < np; i += stride) {
        unsigned p = g_pairs[i];
        int n = (int)(p >> 13);
        int m = (int)(p & 0x1FFFu);
        int a = atomicAdd(&g_ecur[m], 1);
        int ia = g_eoff[m] + a; if (ia < NNZ_CAP) g_edge_nodes[ia] = n;
        int b = atomicAdd(&g_vcur[n], 1);
        int ib = g_voff[n] + b; if (ib < NNZ_CAP) g_node_edges[ib] = m;
    }
}

// ---------------- 5: edge aggregation --------------------------------------
__global__ void __launch_bounds__(128) k_edge_agg() {
    int m = blockIdx.x;
    int beg = g_eoff[m]; int end = g_eoff[m + 1];
    if (end > NNZ_CAP) end = NNZ_CAP;
    if (beg > NNZ_CAP) beg = NNZ_CAP;
    int k = threadIdx.x;
    float sx = 0.f, sy = 0.f;
    int i = beg;
    for (; i + 4 <= end; i += 4) {
        int n0 = g_edge_nodes[i];
        int n1 = g_edge_nodes[i + 1];
        int n2 = g_edge_nodes[i + 2];
        int n3 = g_edge_nodes[i + 3];
        float2 f0 = __bfloat1622float2(g_xbf[n0 * 128 + k]);
        float2 f1 = __bfloat1622float2(g_xbf[n1 * 128 + k]);
        float2 f2 = __bfloat1622float2(g_xbf[n2 * 128 + k]);
        float2 f3 = __bfloat1622float2(g_xbf[n3 * 128 + k]);
        sx += (f0.x + f1.x) + (f2.x + f3.x);
        sy += (f0.y + f1.y) + (f2.y + f3.y);
    }
    for (; i < end; ++i) {
        float2 f0 = __bfloat1622float2(g_xbf[g_edge_nodes[i] * 128 + k]);
        sx += f0.x; sy += f0.y;
    }
    float inv = 1.f / fmaxf((float)g_cnt_e[m], 1.f);
    g_A[m * 128 + k] = __floats2bfloat162_rn(sx * inv, sy * inv);
}

// ---------------- 6: node aggregation --------------------------------------
__global__ void __launch_bounds__(128) k_node_agg() {
    int n = blockIdx.x;
    int beg = g_voff[n]; int end = g_voff[n + 1];
    if (end > NNZ_CAP) end = NNZ_CAP;
    if (beg > NNZ_CAP) beg = NNZ_CAP;
    int k = threadIdx.x;
    float sx = 0.f, sy = 0.f;
    int i = beg;
    for (; i + 4 <= end; i += 4) {
        int m0 = g_node_edges[i];
        int m1 = g_node_edges[i + 1];
        int m2 = g_node_edges[i + 2];
        int m3 = g_node_edges[i + 3];
        float2 f0 = __bfloat1622float2(g_A[m0 * 128 + k]);
        float2 f1 = __bfloat1622float2(g_A[m1 * 128 + k]);
        float2 f2 = __bfloat1622float2(g_A[m2 * 128 + k]);
        float2 f3 = __bfloat1622float2(g_A[m3 * 128 + k]);
        sx += (f0.x + f1.x) + (f2.x + f3.x);
        sy += (f0.y + f1.y) + (f2.y + f3.y);
    }
    for (; i < end; ++i) {
        float2 f0 = __bfloat1622float2(g_A[g_node_edges[i] * 128 + k]);
        sx += f0.x; sy += f0.y;
    }
    float inv = 1.f / fmaxf((float)g_cnt_v[n], 1.f);
    reinterpret_cast<float2*>(g_B)[n * 128 + k] = make_float2(sx * inv, sy * inv);
}

// ---------------- 7a: build A_cat = [bf16(B) | x_hi | x_hi | x_lo] ---------
__global__ void __launch_bounds__(512) k_prep_A(const float2* __restrict__ x2) {
    int row = blockIdx.x;
    int p = threadIdx.x;                 // bf162-pair index 0..511
    __nv_bfloat162* dst = reinterpret_cast<__nv_bfloat162*>(g_Acat) + (size_t)row * 512 + p;
    if (p < 128) {
        float2 f = reinterpret_cast<const float2*>(g_B)[row * 128 + p];
        *dst = __floats2bfloat162_rn(f.x, f.y);
    } else if (p < 384) {
        int q = (p < 256) ? (p - 128) : (p - 256);
        float2 f = x2[row * 128 + q];
        *dst = __floats2bfloat162_rn(f.x, f.y);      // x_hi
    } else {
        int q = p - 384;
        float2 f = x2[row * 128 + q];
        __nv_bfloat16 hx = __float2bfloat16_rn(f.x);
        __nv_bfloat16 hy = __float2bfloat16_rn(f.y);
        __nv_bfloat16 lx = __float2bfloat16_rn(f.x - __bfloat162float(hx));
        __nv_bfloat16 ly = __float2bfloat16_rn(f.y - __bfloat162float(hy));
        *dst = __halves2bfloat162(lx, ly);           // x_lo
    }
}

// ---------------- 7b: build W_t[n, k] = stackedW[k, n] ---------------------
// k blocks: [0:256)=Wn, [256:512)=Wr_hi, [512:768)=Wr_lo, [768:1024)=Wr_hi
__global__ void __launch_bounds__(256) k_prep_W(const float* __restrict__ Wn,
                                               const float* __restrict__ Wr) {
    int i = blockIdx.x * blockDim.x + threadIdx.x;   // i = n*1024 + k
    if (i >= 512 * 1024) return;
    int n = i >> 10;
    int k = i & 1023;
    __nv_bfloat16 v;
    if (k < 256) {
        v = __float2bfloat16_rn(Wn[k * 512 + n]);
    } else if (k < 512) {
        v = __float2bfloat16_rn(Wr[(k - 256) * 512 + n]);                 // hi
    } else if (k < 768) {
        float f = Wr[(k - 512) * 512 + n];
        __nv_bfloat16 h = __float2bfloat16_rn(f);
        v = __float2bfloat16_rn(f - __bfloat162float(h));                 // lo
    } else {
        v = __float2bfloat16_rn(Wr[(k - 768) * 512 + n]);                 // hi
    }
    g_Wt[(size_t)n * 1024 + k] = v;
}

// ---------------- 8: HMMA bf16 GEMM  h = A_cat @ W_t^T ---------------------
// mma.sync.m16n8k16 (sm_80+ PTX, no sm_103a-only features).
// Block tile 128x64, BK=64, 256 threads = 8 warps (4m x 2n), warp tile 32x32.
__device__ __forceinline__ void mma16816(float* c, const uint32_t* a, const uint32_t* b) {
    asm volatile(
        "mma.sync.aligned.m16n8k16.row.col.f32.bf16.bf16.f32 "
        "{%0,%1,%2,%3}, {%4,%5,%6,%7}, {%8,%9}, {%0,%1,%2,%3};\n"
        : "+f"(c[0]), "+f"(c[1]), "+f"(c[2]), "+f"(c[3])
        : "r"(a[0]), "r"(a[1]), "r"(a[2]), "r"(a[3]), "r"(b[0]), "r"(b[1]));
}

#define ASTRIDE 72   // 64 + 8 bf16 pad: fragment LDS banks (4r + lane&3) -> conflict-free

__global__ void __launch_bounds__(256) k_gemm() {
    __shared__ __nv_bfloat16 As[128][ASTRIDE];
    __shared__ __nv_bfloat16 Bs[64][ASTRIDE];
    int tid = threadIdx.x;
    int lane = tid & 31;
    int warp = tid >> 5;
    int warp_m = warp & 3;       // m offset warp_m*32
    int warp_n = warp >> 2;      // n offset warp_n*32
    int rowBase = blockIdx.y * 128;
    int colBase = blockIdx.x * 64;

    int srow = tid >> 3;         // staging row (32 per pass)
    int scol = tid & 7;          // uint4 column within 64-bf16 tile row

    float acc[2][4][4];
    #pragma unroll
    for (int i = 0; i < 2; ++i)
        #pragma unroll
        for (int j = 0; j < 4; ++j)
            #pragma unroll
            for (int q = 0; q < 4; ++q) acc[i][j][q] = 0.f;

    const uint4* gA = reinterpret_cast<const uint4*>(g_Acat);  // row stride 128 uint4
    const uint4* gB = reinterpret_cast<const uint4*>(g_Wt);

    for (int kc = 0; kc < 16; ++kc) {
        int kq = kc * 8 + scol;   // uint4 index into K
        uint4 sa[4], sb[2];
        #pragma unroll
        for (int p = 0; p < 4; ++p)
            sa[p] = gA[(size_t)(rowBase + p * 32 + srow) * 128 + kq];
        #pragma unroll
        for (int p = 0; p < 2; ++p)
            sb[p] = gB[(size_t)(colBase + p * 32 + srow) * 128 + kq];

        __syncthreads();  // previous iteration's fragment reads done
        #pragma unroll
        for (int p = 0; p < 4; ++p)
            *reinterpret_cast<uint4*>(&As[p * 32 + srow][scol * 8]) = sa[p];
        #pragma unroll
        for (int p = 0; p < 2; ++p)
            *reinterpret_cast<uint4*>(&Bs[p * 32 + srow][scol * 8]) = sb[p];
        __syncthreads();

        #pragma unroll
        for (int k0 = 0; k0 < 64; k0 += 16) {
            uint32_t af[2][4], bf[4][2];
            int c = k0 + (lane & 3) * 2;
            #pragma unroll
            for (int tm = 0; tm < 2; ++tm) {
                int r = warp_m * 32 + tm * 16 + (lane >> 2);
                af[tm][0] = *reinterpret_cast<const uint32_t*>(&As[r][c]);
                af[tm][1] = *reinterpret_cast<const uint32_t*>(&As[r + 8][c]);
                af[tm][2] = *reinterpret_cast<const uint32_t*>(&As[r][c + 8]);
                af[tm][3] = *reinterpret_cast<const uint32_t*>(&As[r + 8][c + 8]);
            }
            #pragma unroll
            for (int tn = 0; tn < 4; ++tn) {
                int nr = warp_n * 32 + tn * 8 + (lane >> 2);
                bf[tn][0] = *reinterpret_cast<const uint32_t*>(&Bs[nr][c]);
                bf[tn][1] = *reinterpret_cast<const uint32_t*>(&Bs[nr][c + 8]);
            }
            #pragma unroll
            for (int tm = 0; tm < 2; ++tm)
                #pragma unroll
                for (int tn = 0; tn < 4; ++tn)
                    mma16816(acc[tm][tn], af[tm], bf[tn]);
        }
    }

    // epilogue
    #pragma unroll
    for (int tm = 0; tm < 2; ++tm) {
        int r0 = rowBase + warp_m * 32 + tm * 16 + (lane >> 2);
        #pragma unroll
        for (int tn = 0; tn < 4; ++tn) {
            int c = colBase + warp_n * 32 + tn * 8 + (lane & 3) * 2;
            if (r0 < N_NODES)
                *reinterpret_cast<float2*>(&g_h[(size_t)r0 * D_OUT + c]) =
                    make_float2(acc[tm][tn][0], acc[tm][tn][1]);
            if (r0 + 8 < N_NODES)
                *reinterpret_cast<float2*>(&g_h[(size_t)(r0 + 8) * D_OUT + c]) =
                    make_float2(acc[tm][tn][2], acc[tm][tn][3]);
        }
    }
}

// ---------------- 9: LayerNorm ---------------------------------------------
__global__ void __launch_bounds__(256) k_ln(const float* __restrict__ gamma,
                                            const float* __restrict__ beta,
                                            float* __restrict__ out) {
    int row = blockIdx.x;
    int t = threadIdx.x;
    const float* h = g_h + (size_t)row * D_OUT;
    float v0 = h[t], v1 = h[t + 256];
    float s = v0 + v1;
    float sq = v0 * v0 + v1 * v1;
    #pragma unroll
    for (int o = 16; o > 0; o >>= 1) {
        s  += __shfl_xor_sync(0xffffffffu, s,  o);
        sq += __shfl_xor_sync(0xffffffffu, sq, o);
    }
    __shared__ float ssum[8], ssq[8];
    __shared__ float s_mu, s_inv;
    int w = t >> 5, l = t & 31;
    if (l == 0) { ssum[w] = s; ssq[w] = sq; }
    __syncthreads();
    if (t == 0) {
        float ts = 0.f, tq = 0.f;
        #pragma unroll
        for (int i = 0; i < 8; ++i) { ts += ssum[i]; tq += ssq[i]; }
        float mu = ts * (1.f / (float)D_OUT);
        float var = tq * (1.f / (float)D_OUT) - mu * mu;
        s_mu = mu;
        s_inv = rsqrtf(var + 1e-5f);
    }
    __syncthreads();
    float mu = s_mu, inv = s_inv;
    out[(size_t)row * D_OUT + t]       = (v0 - mu) * inv * gamma[t]       + beta[t];
    out[(size_t)row * D_OUT + t + 256] = (v1 - mu) * inv * gamma[t + 256] + beta[t + 256];
}

// ---------------- launch ----------------------------------------------------
extern "C" void kernel_launch(void* const* d_in, const int* in_sizes, int n_in,
                              void* d_out, int out_size) {
    const float* x     = (const float*)d_in[0];
    const float* H     = (const float*)d_in[1];
    const float* Wn    = (const float*)d_in[2];
    const float* Wr    = (const float*)d_in[3];
    const float* gamma = (const float*)d_in[4];
    const float* beta  = (const float*)d_in[5];
    float* out = (float*)d_out;

    k_zero<<<(N_NODES + 255) / 256, 256>>>();
    k_xcast<<<(N_NODES * (D_IN / 2) + 255) / 256, 256>>>((const float2*)x);

    const int total4 = N_NODES * (M_EDGES / 4);
    k_count_pairs<<<(total4 + 255) / 256, 256>>>((const float4*)H);
    k_scan2<<<1, 1024>>>();
    k_scatter<<<2048, 256>>>();

    k_edge_agg<<<M_EDGES, 128>>>();
    k_node_agg<<<N_NODES, 128>>>();

    k_prep_W<<<(512 * 1024 + 255) / 256, 256>>>(Wn, Wr);
    k_prep_A<<<N_NODES, 512>>>((const float2*)x);

    dim3 ggrid(D_OUT / 64, N_PAD / 128);   // (8, 157)
    k_gemm<<<ggrid, 256>>>();

    k_ln<<<N_NODES, 256>>>(gamma, beta, out);
}

// round 13
// speedup vs baseline: 1.6299x; 1.0955x over previous
#include <cuda_runtime.h>
#include <cuda_bf16.h>
#include <cuda_fp16.h>
#include <cuda_fp8.h>
#include <cstdint>

#define N_NODES 20000
#define M_EDGES 5000
#define D_IN    256
#define D_OUT   512
#define NNZ_CAP 5400000
#define N_PAD   20096            // 157 * 128

// ===================== fp8 helpers =========================================
__device__ __forceinline__ float2 f8x2_to_f2(unsigned short v) {
    __half2_raw hr = __nv_cvt_fp8x2_to_halfraw2((__nv_fp8x2_storage_t)v, __NV_E4M3);
    __half2 h = *reinterpret_cast<__half2*>(&hr);
    return __half22float2(h);
}
__device__ __forceinline__ unsigned short f2_to_f8x2(float2 f) {
    return (unsigned short)__nv_cvt_float2_to_fp8x2(f, __NV_SATFINITE, __NV_E4M3);
}

// ===================== scratch (static device globals) =====================
__device__ int g_cnt_e[M_EDGES];
__device__ int g_cnt_v[N_NODES];
__device__ int g_eoff[M_EDGES + 1];
__device__ int g_voff[N_NODES + 1];
__device__ int g_ecur[M_EDGES];
__device__ int g_vcur[N_NODES];
__device__ int g_npairs;
__device__ unsigned int g_pairs[NNZ_CAP];      // (n << 13) | m
__device__ int g_edge_nodes[NNZ_CAP];
__device__ int g_node_edges[NNZ_CAP];
__device__ unsigned short g_xf8[N_NODES * 128];   // x in fp8x2 (5 MB, L2-resident)
__device__ unsigned short g_Af8[M_EDGES * 128];   // edge feats fp8x2 (1.25 MB)
__device__ float g_B[N_NODES * D_IN];
__device__ float g_h[N_NODES * D_OUT];
__device__ __nv_bfloat16 g_Acat[(size_t)N_PAD * 1024];   // [Bbf | x_hi | x_hi | x_lo]
__device__ __nv_bfloat16 g_Wt[512 * 1024];               // transposed stacked weights

// ---------------- 1: fused init: zero counters + x -> fp8 ------------------
__global__ void k_init(const float2* __restrict__ x2) {
    int i = blockIdx.x * blockDim.x + threadIdx.x;
    if (i < M_EDGES) { g_cnt_e[i] = 0; g_ecur[i] = 0; }
    if (i < N_NODES) { g_cnt_v[i] = 0; g_vcur[i] = 0; }
    if (i == 0) g_npairs = 0;
    const int total = N_NODES * 128;
    int stride = gridDim.x * blockDim.x;
    for (int j = i; j < total; j += stride)
        g_xf8[j] = f2_to_f8x2(x2[j]);
}

// ---------------- 2: single H pass: counts + packed nonzero pairs ----------
__global__ void k_count_pairs(const float4* __restrict__ H4) {
    int i = blockIdx.x * blockDim.x + threadIdx.x;
    const int total = N_NODES * (M_EDGES / 4);
    float4 v = make_float4(0.f, 0.f, 0.f, 0.f);
    if (i < total) v = H4[i];
    int base = i * 4;
    int n = base / M_EDGES;
    int m = base - n * M_EDGES;
    int ms[4]; int vc = 0;
    if (v.x != 0.f) { atomicAdd(&g_cnt_e[m + 0], 1); ms[vc++] = m + 0; }
    if (v.y != 0.f) { atomicAdd(&g_cnt_e[m + 1], 1); ms[vc++] = m + 1; }
    if (v.z != 0.f) { atomicAdd(&g_cnt_e[m + 2], 1); ms[vc++] = m + 2; }
    if (v.w != 0.f) { atomicAdd(&g_cnt_e[m + 3], 1); ms[vc++] = m + 3; }
    const unsigned full = 0xffffffffu;
    int lane = threadIdx.x & 31;
    // node-degree: one atomic per warp when the warp is row-uniform (~97%)
    int n0 = __shfl_sync(full, n, 0);
    bool uni = __all_sync(full, n == n0);
    if (uni) {
        int vsum = vc;
        #pragma unroll
        for (int o = 16; o > 0; o >>= 1) vsum += __shfl_xor_sync(full, vsum, o);
        if (lane == 0 && vsum) atomicAdd(&g_cnt_v[n0], vsum);
    } else if (vc) {
        atomicAdd(&g_cnt_v[n], vc);
    }
    // warp-aggregated pair append
    int incl = vc;
    #pragma unroll
    for (int o = 1; o < 32; o <<= 1) {
        int t = __shfl_up_sync(full, incl, o);
        if (lane >= o) incl += t;
    }
    int tot = __shfl_sync(full, incl, 31);
    int wbase = 0;
    if (lane == 31 && tot) wbase = atomicAdd(&g_npairs, tot);
    wbase = __shfl_sync(full, wbase, 31);
    int off = wbase + incl - vc;
    for (int j = 0; j < vc; ++j)
        if (off + j < NNZ_CAP) g_pairs[off + j] = ((unsigned)n << 13) | (unsigned)ms[j];
}

// ---------------- 3: both exclusive scans, O(n), 2 parallel blocks ---------
__device__ __forceinline__ void scan_phase(const int* cnt, int* off, int len,
                                           int* part) {
    int t = threadIdx.x;
    int chunk = (len + 1023) / 1024;
    int beg = t * chunk;
    int end = beg + chunk; if (end > len) end = len;
    if (beg > len) beg = len;
    int s = 0;
    for (int i = beg; i < end; ++i) s += cnt[i];
    part[t] = s;
    __syncthreads();
    #pragma unroll
    for (int o = 1; o < 1024; o <<= 1) {
        int v = (t >= o) ? part[t - o] : 0;
        __syncthreads();
        part[t] += v;
        __syncthreads();
    }
    int run = part[t] - s;   // exclusive prefix of this chunk
    for (int i = beg; i < end; ++i) { off[i] = run; run += cnt[i]; }
    if (t == 1023) off[len] = part[1023];
}
__global__ void k_scan2() {
    __shared__ int part[1024];
    if (blockIdx.x == 0) scan_phase(g_cnt_e, g_eoff, M_EDGES, part);
    else                 scan_phase(g_cnt_v, g_voff, N_NODES, part);
}

// ---------------- 4: scatter pairs into CSC + CSR (grid-stride) ------------
__global__ void k_scatter() {
    int np = g_npairs; if (np > NNZ_CAP) np = NNZ_CAP;
    int stride = gridDim.x * blockDim.x;
    for (int i = blockIdx.x * blockDim.x + threadIdx.x; i < np; i += stride) {
        unsigned p = g_pairs[i];
        int n = (int)(p >> 13);
        int m = (int)(p & 0x1FFFu);
        int a = atomicAdd(&g_ecur[m], 1);
        int ia = g_eoff[m] + a; if (ia < NNZ_CAP) g_edge_nodes[ia] = n;
        int b = atomicAdd(&g_vcur[n], 1);
        int ib = g_voff[n] + b; if (ib < NNZ_CAP) g_node_edges[ib] = m;
    }
}

// ---------------- 5: edge aggregation (fp8 gathers) ------------------------
__global__ void __launch_bounds__(128) k_edge_agg() {
    int m = blockIdx.x;
    int beg = g_eoff[m]; int end = g_eoff[m + 1];
    if (end > NNZ_CAP) end = NNZ_CAP;
    if (beg > NNZ_CAP) beg = NNZ_CAP;
    int k = threadIdx.x;
    float sx = 0.f, sy = 0.f;
    int i = beg;
    for (; i + 4 <= end; i += 4) {
        int n0 = g_edge_nodes[i];
        int n1 = g_edge_nodes[i + 1];
        int n2 = g_edge_nodes[i + 2];
        int n3 = g_edge_nodes[i + 3];
        float2 f0 = f8x2_to_f2(g_xf8[n0 * 128 + k]);
        float2 f1 = f8x2_to_f2(g_xf8[n1 * 128 + k]);
        float2 f2 = f8x2_to_f2(g_xf8[n2 * 128 + k]);
        float2 f3 = f8x2_to_f2(g_xf8[n3 * 128 + k]);
        sx += (f0.x + f1.x) + (f2.x + f3.x);
        sy += (f0.y + f1.y) + (f2.y + f3.y);
    }
    for (; i < end; ++i) {
        float2 f0 = f8x2_to_f2(g_xf8[g_edge_nodes[i] * 128 + k]);
        sx += f0.x; sy += f0.y;
    }
    float inv = 1.f / fmaxf((float)g_cnt_e[m], 1.f);
    g_Af8[m * 128 + k] = f2_to_f8x2(make_float2(sx * inv, sy * inv));
}

// ---------------- 6: node aggregation (fp8 gathers, fp32 out) --------------
__global__ void __launch_bounds__(128) k_node_agg() {
    int n = blockIdx.x;
    int beg = g_voff[n]; int end = g_voff[n + 1];
    if (end > NNZ_CAP) end = NNZ_CAP;
    if (beg > NNZ_CAP) beg = NNZ_CAP;
    int k = threadIdx.x;
    float sx = 0.f, sy = 0.f;
    int i = beg;
    for (; i + 4 <= end; i += 4) {
        int m0 = g_node_edges[i];
        int m1 = g_node_edges[i + 1];
        int m2 = g_node_edges[i + 2];
        int m3 = g_node_edges[i + 3];
        float2 f0 = f8x2_to_f2(g_Af8[m0 * 128 + k]);
        float2 f1 = f8x2_to_f2(g_Af8[m1 * 128 + k]);
        float2 f2 = f8x2_to_f2(g_Af8[m2 * 128 + k]);
        float2 f3 = f8x2_to_f2(g_Af8[m3 * 128 + k]);
        sx += (f0.x + f1.x) + (f2.x + f3.x);
        sy += (f0.y + f1.y) + (f2.y + f3.y);
    }
    for (; i < end; ++i) {
        float2 f0 = f8x2_to_f2(g_Af8[g_node_edges[i] * 128 + k]);
        sx += f0.x; sy += f0.y;
    }
    float inv = 1.f / fmaxf((float)g_cnt_v[n], 1.f);
    reinterpret_cast<float2*>(g_B)[n * 128 + k] = make_float2(sx * inv, sy * inv);
}

// ---------------- 7a: build A_cat = [bf16(B) | x_hi | x_hi | x_lo] ---------
__global__ void __launch_bounds__(512) k_prep_A(const float2* __restrict__ x2) {
    int row = blockIdx.x;
    int p = threadIdx.x;                 // bf162-pair index 0..511
    __nv_bfloat162* dst = reinterpret_cast<__nv_bfloat162*>(g_Acat) + (size_t)row * 512 + p;
    if (p < 128) {
        float2 f = reinterpret_cast<const float2*>(g_B)[row * 128 + p];
        *dst = __floats2bfloat162_rn(f.x, f.y);
    } else if (p < 384) {
        int q = (p < 256) ? (p - 128) : (p - 256);
        float2 f = x2[row * 128 + q];
        *dst = __floats2bfloat162_rn(f.x, f.y);      // x_hi
    } else {
        int q = p - 384;
        float2 f = x2[row * 128 + q];
        __nv_bfloat16 hx = __float2bfloat16_rn(f.x);
        __nv_bfloat16 hy = __float2bfloat16_rn(f.y);
        __nv_bfloat16 lx = __float2bfloat16_rn(f.x - __bfloat162float(hx));
        __nv_bfloat16 ly = __float2bfloat16_rn(f.y - __bfloat162float(hy));
        *dst = __halves2bfloat162(lx, ly);           // x_lo
    }
}

// ---------------- 7b: build W_t[n, k] = stackedW[k, n] ---------------------
// k blocks: [0:256)=Wn, [256:512)=Wr_hi, [512:768)=Wr_lo, [768:1024)=Wr_hi
__global__ void __launch_bounds__(256) k_prep_W(const float* __restrict__ Wn,
                                               const float* __restrict__ Wr) {
    int i = blockIdx.x * blockDim.x + threadIdx.x;   // i = n*1024 + k
    if (i >= 512 * 1024) return;
    int n = i >> 10;
    int k = i & 1023;
    __nv_bfloat16 v;
    if (k < 256) {
        v = __float2bfloat16_rn(Wn[k * 512 + n]);
    } else if (k < 512) {
        v = __float2bfloat16_rn(Wr[(k - 256) * 512 + n]);                 // hi
    } else if (k < 768) {
        float f = Wr[(k - 512) * 512 + n];
        __nv_bfloat16 h = __float2bfloat16_rn(f);
        v = __float2bfloat16_rn(f - __bfloat162float(h));                 // lo
    } else {
        v = __float2bfloat16_rn(Wr[(k - 768) * 512 + n]);                 // hi
    }
    g_Wt[(size_t)n * 1024 + k] = v;
}

// ---------------- 8: HMMA bf16 GEMM  h = A_cat @ W_t^T ---------------------
__device__ __forceinline__ void mma16816(float* c, const uint32_t* a, const uint32_t* b) {
    asm volatile(
        "mma.sync.aligned.m16n8k16.row.col.f32.bf16.bf16.f32 "
        "{%0,%1,%2,%3}, {%4,%5,%6,%7}, {%8,%9}, {%0,%1,%2,%3};\n"
        : "+f"(c[0]), "+f"(c[1]), "+f"(c[2]), "+f"(c[3])
        : "r"(a[0]), "r"(a[1]), "r"(a[2]), "r"(a[3]), "r"(b[0]), "r"(b[1]));
}

#define ASTRIDE 72   // 64 + 8 bf16 pad: fragment LDS banks (4r + lane&3) -> conflict-free

__global__ void __launch_bounds__(256) k_gemm() {
    __shared__ __nv_bfloat16 As[128][ASTRIDE];
    __shared__ __nv_bfloat16 Bs[64][ASTRIDE];
    int tid = threadIdx.x;
    int lane = tid & 31;
    int warp = tid >> 5;
    int warp_m = warp & 3;       // m offset warp_m*32
    int warp_n = warp >> 2;      // n offset warp_n*32
    int rowBase = blockIdx.y * 128;
    int colBase = blockIdx.x * 64;

    int srow = tid >> 3;         // staging row (32 per pass)
    int scol = tid & 7;          // uint4 column within 64-bf16 tile row

    float acc[2][4][4];
    #pragma unroll
    for (int i = 0; i < 2; ++i)
        #pragma unroll
        for (int j = 0; j < 4; ++j)
            #pragma unroll
            for (int q = 0; q < 4; ++q) acc[i][j][q] = 0.f;

    const uint4* gA = reinterpret_cast<const uint4*>(g_Acat);  // row stride 128 uint4
    const uint4* gB = reinterpret_cast<const uint4*>(g_Wt);

    for (int kc = 0; kc < 16; ++kc) {
        int kq = kc * 8 + scol;   // uint4 index into K
        uint4 sa[4], sb[2];
        #pragma unroll
        for (int p = 0; p < 4; ++p)
            sa[p] = gA[(size_t)(rowBase + p * 32 + srow) * 128 + kq];
        #pragma unroll
        for (int p = 0; p < 2; ++p)
            sb[p] = gB[(size_t)(colBase + p * 32 + srow) * 128 + kq];

        __syncthreads();  // previous iteration's fragment reads done
        #pragma unroll
        for (int p = 0; p < 4; ++p)
            *reinterpret_cast<uint4*>(&As[p * 32 + srow][scol * 8]) = sa[p];
        #pragma unroll
        for (int p = 0; p < 2; ++p)
            *reinterpret_cast<uint4*>(&Bs[p * 32 + srow][scol * 8]) = sb[p];
        __syncthreads();

        #pragma unroll
        for (int k0 = 0; k0 < 64; k0 += 16) {
            uint32_t af[2][4], bf[4][2];
            int c = k0 + (lane & 3) * 2;
            #pragma unroll
            for (int tm = 0; tm < 2; ++tm) {
                int r = warp_m * 32 + tm * 16 + (lane >> 2);
                af[tm][0] = *reinterpret_cast<const uint32_t*>(&As[r][c]);
                af[tm][1] = *reinterpret_cast<const uint32_t*>(&As[r + 8][c]);
                af[tm][2] = *reinterpret_cast<const uint32_t*>(&As[r][c + 8]);
                af[tm][3] = *reinterpret_cast<const uint32_t*>(&As[r + 8][c + 8]);
            }
            #pragma unroll
            for (int tn = 0; tn < 4; ++tn) {
                int nr = warp_n * 32 + tn * 8 + (lane >> 2);
                bf[tn][0] = *reinterpret_cast<const uint32_t*>(&Bs[nr][c]);
                bf[tn][1] = *reinterpret_cast<const uint32_t*>(&Bs[nr][c + 8]);
            }
            #pragma unroll
            for (int tm = 0; tm < 2; ++tm)
                #pragma unroll
                for (int tn = 0; tn < 4; ++tn)
                    mma16816(acc[tm][tn], af[tm], bf[tn]);
        }
    }

    // epilogue
    #pragma unroll
    for (int tm = 0; tm < 2; ++tm) {
        int r0 = rowBase + warp_m * 32 + tm * 16 + (lane >> 2);
        #pragma unroll
        for (int tn = 0; tn < 4; ++tn) {
            int c = colBase + warp_n * 32 + tn * 8 + (lane & 3) * 2;
            if (r0 < N_NODES)
                *reinterpret_cast<float2*>(&g_h[(size_t)r0 * D_OUT + c]) =
                    make_float2(acc[tm][tn][0], acc[tm][tn][1]);
            if (r0 + 8 < N_NODES)
                *reinterpret_cast<float2*>(&g_h[(size_t)(r0 + 8) * D_OUT + c]) =
                    make_float2(acc[tm][tn][2], acc[tm][tn][3]);
        }
    }
}

// ---------------- 9: LayerNorm ---------------------------------------------
__global__ void __launch_bounds__(256) k_ln(const float* __restrict__ gamma,
                                            const float* __restrict__ beta,
                                            float* __restrict__ out) {
    int row = blockIdx.x;
    int t = threadIdx.x;
    const float* h = g_h + (size_t)row * D_OUT;
    float v0 = h[t], v1 = h[t + 256];
    float s = v0 + v1;
    float sq = v0 * v0 + v1 * v1;
    #pragma unroll
    for (int o = 16; o > 0; o >>= 1) {
        s  += __shfl_xor_sync(0xffffffffu, s,  o);
        sq += __shfl_xor_sync(0xffffffffu, sq, o);
    }
    __shared__ float ssum[8], ssq[8];
    __shared__ float s_mu, s_inv;
    int w = t >> 5, l = t & 31;
    if (l == 0) { ssum[w] = s; ssq[w] = sq; }
    __syncthreads();
    if (t == 0) {
        float ts = 0.f, tq = 0.f;
        #pragma unroll
        for (int i = 0; i < 8; ++i) { ts += ssum[i]; tq += ssq[i]; }
        float mu = ts * (1.f / (float)D_OUT);
        float var = tq * (1.f / (float)D_OUT) - mu * mu;
        s_mu = mu;
        s_inv = rsqrtf(var + 1e-5f);
    }
    __syncthreads();
    float mu = s_mu, inv = s_inv;
    out[(size_t)row * D_OUT + t]       = (v0 - mu) * inv * gamma[t]       + beta[t];
    out[(size_t)row * D_OUT + t + 256] = (v1 - mu) * inv * gamma[t + 256] + beta[t + 256];
}

// ---------------- launch ----------------------------------------------------
extern "C" void kernel_launch(void* const* d_in, const int* in_sizes, int n_in,
                              void* d_out, int out_size) {
    const float* x     = (const float*)d_in[0];
    const float* H     = (const float*)d_in[1];
    const float* Wn    = (const float*)d_in[2];
    const float* Wr    = (const float*)d_in[3];
    const float* gamma = (const float*)d_in[4];
    const float* beta  = (const float*)d_in[5];
    float* out = (float*)d_out;

    k_init<<<10000, 256>>>((const float2*)x);

    const int total4 = N_NODES * (M_EDGES / 4);
    k_count_pairs<<<(total4 + 255) / 256, 256>>>((const float4*)H);
    k_scan2<<<2, 1024>>>();
    k_scatter<<<2048, 256>>>();

    k_edge_agg<<<M_EDGES, 128>>>();
    k_node_agg<<<N_NODES, 128>>>();

    k_prep_W<<<(512 * 1024 + 255) / 256, 256>>>(Wn, Wr);
    k_prep_A<<<N_NODES, 512>>>((const float2*)x);

    dim3 ggrid(D_OUT / 64, N_PAD / 128);   // (8, 157)
    k_gemm<<<ggrid, 256>>>();

    k_ln<<<N_NODES, 256>>>(gamma, beta, out);
}